// round 12
// baseline (speedup 1.0000x reference)
#include <cuda_runtime.h>
#include <cstdint>
#include <float.h>

// Problem constants
#define Bn    8
#define Nn    256
#define Dd    128
#define MIDn  128
#define FEATn 256   // 2*D
#define NTOT  (Bn * Nn)     // 2048 (b,j) tiles
#define GRID  148           // persistent: 1 CTA per SM

// Scratch (device globals; no runtime allocation allowed)
__device__ float g_msg1[Bn * Nn * MIDn];
__device__ float g_msg2[Bn * Nn * MIDn];
__device__ float g_msgg[Bn * MIDn];
__device__ float g_base[Bn * Nn * MIDn];
__device__ unsigned g_WeTpack[MIDn * Dd];       // We^T fragment-packed (tf32 bits)

// ---------------- PTX helpers (arch-agnostic, sm_80+) --------------------
__device__ __forceinline__ uint32_t smem_u32(const void* p) {
    uint32_t a;
    asm("{ .reg .u64 t; cvta.to.shared.u64 t, %1; cvt.u32.u64 %0, t; }"
        : "=r"(a) : "l"(p));
    return a;
}
__device__ __forceinline__ void cp16(uint32_t dst, const void* src) {
    asm volatile("cp.async.cg.shared.global [%0], [%1], 16;"
                 :: "r"(dst), "l"(src) : "memory");
}
__device__ __forceinline__ void cp_commit() {
    asm volatile("cp.async.commit_group;" ::: "memory");
}
template <int N> __device__ __forceinline__ void cp_wait() {
    asm volatile("cp.async.wait_group %0;" :: "n"(N) : "memory");
}
__device__ __forceinline__ unsigned tf32r(float x) {
    unsigned u;
    asm("cvt.rna.tf32.f32 %0, %1;" : "=r"(u) : "f"(x));
    return u;
}
__device__ __forceinline__ void mma8(float* c, uint4 a, unsigned b0, unsigned b1) {
    asm volatile(
        "mma.sync.aligned.m16n8k8.row.col.f32.tf32.tf32.f32 "
        "{%0,%1,%2,%3},{%4,%5,%6,%7},{%8,%9},{%0,%1,%2,%3};"
        : "+f"(c[0]), "+f"(c[1]), "+f"(c[2]), "+f"(c[3])
        : "r"(a.x), "r"(a.y), "r"(a.z), "r"(a.w), "r"(b0), "r"(b1));
}

// ---------------- smem layout (bytes), 4-deep ring ------------------------
#define EPADB    576    // 144 floats: LDS.128 conflict-free (16g+4t per phase)
#define ECHUNKB  (32 * EPADB)               // 18432
#define M2PADB   528    // 132 floats: LDS.32 conflict-free (8t+g)
#define M2CHUNKB (32 * M2PADB)              // 16896
#define SM_E     0                          // 4 * 18432 = 73728
#define SM_M     73728                      // 4 * 16896 = 67584
#define SM_IDX   141312                     // 4 * 256 ints = 4096
#define SM_CNT   145408                     // 4 ints (pad 128)
#define SM_BEST  145536                     // 2 * 128 floats = 1024
#define SM_TOTAL 146560

// ========================================================================
// Fused aux kernel (512 threads/block, 296 blocks):
//   [0,256)   : prep (msg1,msg2,base)
//   [256,288) : pack We^T A-fragments (deep k-relabel for LDS.128 B path)
//   [288,296) : msgg (tid<128)
// ========================================================================
__global__ __launch_bounds__(512) void aux_kernel(
    const float* __restrict__ hidden, const float* __restrict__ nfeat,
    const float* __restrict__ gfeat,
    const float* __restrict__ W1, const float* __restrict__ b1,
    const float* __restrict__ W2, const float* __restrict__ b2,
    const float* __restrict__ We,
    const float* __restrict__ Wg, const float* __restrict__ bg,
    const float* __restrict__ Wo1, const float* __restrict__ bo1,
    const float* __restrict__ bo2)
{
    const int tid = threadIdx.x;
    if (blockIdx.x >= 288) {                       // ---- msgg ----
        if (tid < 128) {
            const int b = blockIdx.x - 288, m = tid;
            float acc = bg[m];
            #pragma unroll 8
            for (int k = 0; k < Dd; k++)
                acc = fmaf(gfeat[b * Dd + k], __ldg(&Wg[k * MIDn + m]), acc);
            g_msgg[b * MIDn + m] = acc;
        }
        return;
    }
    if (blockIdx.x >= 256) {                       // ---- A pack ----
        const int idx = (blockIdx.x - 256) * 512 + tid;   // 0..16383
        const int blk = idx >> 7;                  // mtg16*16 + kt
        const int mtg = blk >> 4, kt = blk & 15;
        const int l = (idx >> 2) & 31, e = idx & 3;
        const int m = mtg * 16 + (l >> 2) + (e & 1) * 8;
        // deep relabel: slot (t + (e>>1)*4) of step kt holds physical
        // k = 16*(kt>>1) + 4t + 2*(kt&1) + (e>>1)
        const int k = ((kt >> 1) << 4) + 4 * (l & 3) + ((kt & 1) << 1)
                    + (e >> 1);
        g_WeTpack[idx] = tf32r(We[k * MIDn + m]);
        return;
    }
    // ---- prep: 8 rows, f split 4 ways ----
    __shared__ float fs[8 * FEATn];
    __shared__ float red[3][3 * 1024];
    const int m = tid & 127, h = tid >> 7;
    const int row0 = blockIdx.x * 8;

    for (int idx = tid; idx < 8 * FEATn; idx += 512) {
        int r = idx >> 8, c = idx & 255;
        fs[idx] = (c < Dd) ? nfeat[(row0 + r) * Dd + c]
                           : hidden[(row0 + r) * Dd + (c - Dd)];
    }
    __syncthreads();

    float a1[8], a2[8], ao[8];
    #pragma unroll
    for (int r = 0; r < 8; r++) { a1[r] = 0.f; a2[r] = 0.f; ao[r] = 0.f; }

    const int fbase = h * 64;
    #pragma unroll 4
    for (int ff = 0; ff < 64; ff++) {
        const int f = fbase + ff;
        const float w1 = __ldg(&W1[f * MIDn + m]);
        const float w2 = __ldg(&W2[f * MIDn + m]);
        const float wo = __ldg(&Wo1[f * MIDn + m]);
        #pragma unroll
        for (int r = 0; r < 8; r++) {
            const float s = fs[r * FEATn + f];
            a1[r] = fmaf(s, w1, a1[r]);
            a2[r] = fmaf(s, w2, a2[r]);
            ao[r] = fmaf(s, wo, ao[r]);
        }
    }
    if (h > 0) {
        #pragma unroll
        for (int r = 0; r < 8; r++) {
            red[h - 1][0 * 1024 + r * 128 + m] = a1[r];
            red[h - 1][1 * 1024 + r * 128 + m] = a2[r];
            red[h - 1][2 * 1024 + r * 128 + m] = ao[r];
        }
    }
    __syncthreads();
    if (h == 0) {
        const float bb1 = b1[m], bb2 = b2[m], bbo = bo1[m] + bo2[m];
        #pragma unroll
        for (int r = 0; r < 8; r++) {
            const int row = row0 + r;
            const int o = r * 128 + m;
            g_msg1[row * MIDn + m] = a1[r] + red[0][o] + red[1][o]
                                   + red[2][o] + bb1;
            g_msg2[row * MIDn + m] = a2[r] + red[0][1024 + o] + red[1][1024 + o]
                                   + red[2][1024 + o] + bb2;
            g_base[row * MIDn + m] = ao[r] + red[0][2048 + o] + red[1][2048 + o]
                                   + red[2][2048 + o] + bbo;
        }
    }
}

// ========================================================================
// Persistent main kernel: 1 CTA/SM, 256 threads = 4 m-groups x 2 n-groups.
// 4-deep chunk ring, stage-3-ahead state machine crossing tile boundaries.
// ========================================================================
__device__ __forceinline__ void stage_chunk(uint32_t sb, const float* ebj,
                                            const float* m2g,
                                            const int* idxp, int qs, int tid)
{
    const int buf = qs & 3;
    const uint32_t ebuf = sb + SM_E + buf * ECHUNKB;
    const uint32_t mbuf = sb + SM_M + buf * M2CHUNKB;
    const int row = tid >> 3, seg = tid & 7;
    const long i = idxp[row];
    const float* esrc = ebj + i * (Nn * Dd);
    const float* msrc = m2g + i * MIDn;
    #pragma unroll
    for (int q = 0; q < 4; q++) {
        const int s = seg + 8 * q;
        cp16(ebuf + row * EPADB + s * 16, esrc + s * 4);
        cp16(mbuf + row * M2PADB + s * 16, msrc + s * 4);
    }
}

__device__ __forceinline__ int build_list(const float* __restrict__ adjcol,
                                          int* idxd, int* cntd, int tid)
{
    if (tid == 0) *cntd = 0;
    __syncthreads();
    {
        const int w = tid >> 5, l = tid & 31;
        const int i = w * 32 + l;
        const float a = adjcol[(long)i * Nn];
        const unsigned mask = __ballot_sync(0xFFFFFFFFu, a != 0.f);
        int basep = 0;
        if (l == 0) basep = atomicAdd(cntd, __popc(mask));
        basep = __shfl_sync(0xFFFFFFFFu, basep, 0);
        if (a != 0.f) idxd[basep + __popc(mask & ((1u << l) - 1))] = i;
    }
    __syncthreads();
    const int cnt = *cntd;
    for (int s = cnt + tid; s < 256; s += 256) idxd[s] = 0;
    __syncthreads();
    return cnt;
}

struct StageState { int it, ts, cs, ncs; };

__device__ __forceinline__ void try_stage_one(
    uint32_t sb, const float* efeat, const float* adj,
    int* idxr, int* cntr, StageState& S, int& qs, int tid)
{
    while (S.cs >= S.ncs && S.it < NTOT) {
        S.it += GRID; S.ts++;
        if (S.it < NTOT) {
            const int b = S.it >> 8, j = S.it & 255;
            const int cnt = build_list(adj + (long)b * Nn * Nn + j,
                                       idxr + (S.ts & 3) * 256,
                                       cntr + (S.ts & 3), tid);
            S.ncs = (cnt + 31) >> 5; S.cs = 0;
        }
    }
    if (S.it < NTOT) {
        const int b = S.it >> 8, j = S.it & 255;
        stage_chunk(sb, efeat + (long)b * (Nn * Nn * Dd) + (long)j * Dd,
                    g_msg2 + ((long)b << 15),
                    idxr + (S.ts & 3) * 256 + S.cs * 32, qs, tid);
        S.cs++; qs++;
    }
    cp_commit();
}

__global__ __launch_bounds__(256, 1) void main_kernel(
    const float* __restrict__ efeat, const float* __restrict__ adj,
    const float* __restrict__ be,    const float* __restrict__ Wo2,
    float* __restrict__ out)
{
    extern __shared__ __align__(16) char smem[];
    const uint32_t sb = smem_u32(smem);
    const int tid = threadIdx.x;
    const int w = tid >> 5, l = tid & 31, g = l >> 2, t = l & 3;
    const int wm = w & 3, wn = w >> 2;            // m-group, n-group

    int* idxr = (int*)(smem + SM_IDX);
    int* cntr = (int*)(smem + SM_CNT);
    float* bestsm = (float*)(smem + SM_BEST);     // [2][128]

    // A fragments for this warp's 32-row m-tile (128 regs)
    uint4 A[2][16];
    #pragma unroll
    for (int mt = 0; mt < 2; mt++)
        #pragma unroll
        for (int kt = 0; kt < 16; kt++)
            A[mt][kt] = *(const uint4*)(g_WeTpack
                         + (((wm * 2 + mt) * 16 + kt) << 7) + (l << 2));

    // staging state; first walk builds tile blockIdx.x into ring slot 0
    StageState S; S.it = (int)blockIdx.x - GRID; S.ts = -1; S.cs = 0; S.ncs = 0;
    int qs = 0;
    try_stage_one(sb, efeat, adj, idxr, cntr, S, qs, tid);
    try_stage_one(sb, efeat, adj, idxr, cntr, S, qs, tid);
    try_stage_one(sb, efeat, adj, idxr, cntr, S, qs, tid);

    int it = blockIdx.x, ts = 0, qc = 0;
    while (it < NTOT) {
        const int b = it >> 8;
        const int cnt = cntr[ts & 3];
        const int nc = (cnt + 31) >> 5;

        float cm[4], best[4];
        #pragma unroll
        for (int s = 0; s < 4; s++) {
            const int m = wm * 32 + (s >> 1) * 16 + (s & 1) * 8 + g;
            cm[s] = g_msg1[it * MIDn + m] + g_msgg[b * MIDn + m] + be[m];
            best[s] = -FLT_MAX;
        }

        #pragma unroll 1
        for (int cc = 0; cc < nc; cc++) {
            cp_wait<2>();
            __syncthreads();
            const int buf = qc & 3;
            const char* eb = smem + SM_E + buf * ECHUNKB;
            const float* m2s = (const float*)(smem + SM_M + buf * M2CHUNKB);

            // acc init = msg2 + cst
            float acc[2][2][4];
            #pragma unroll
            for (int nt = 0; nt < 2; nt++) {
                const int il = wn * 16 + nt * 8 + 2 * t;
                #pragma unroll
                for (int mt = 0; mt < 2; mt++) {
                    const int mlo = wm * 32 + mt * 16 + g;
                    acc[mt][nt][0] = m2s[il * 132 + mlo] + cm[mt * 2];
                    acc[mt][nt][1] = m2s[(il + 1) * 132 + mlo] + cm[mt * 2];
                    acc[mt][nt][2] = m2s[il * 132 + mlo + 8] + cm[mt * 2 + 1];
                    acc[mt][nt][3] = m2s[(il + 1) * 132 + mlo + 8] + cm[mt * 2 + 1];
                }
            }

            #pragma unroll
            for (int ktp = 0; ktp < 8; ktp++) {
                #pragma unroll
                for (int nt = 0; nt < 2; nt++) {
                    const float4 f = *(const float4*)(eb
                        + (wn * 16 + nt * 8 + g) * EPADB + ktp * 64 + t * 16);
                    const unsigned f0 = __float_as_uint(f.x);
                    const unsigned f1 = __float_as_uint(f.y);
                    const unsigned f2 = __float_as_uint(f.z);
                    const unsigned f3 = __float_as_uint(f.w);
                    mma8(acc[0][nt], A[0][2 * ktp], f0, f1);
                    mma8(acc[1][nt], A[1][2 * ktp], f0, f1);
                    mma8(acc[0][nt], A[0][2 * ktp + 1], f2, f3);
                    mma8(acc[1][nt], A[1][2 * ktp + 1], f2, f3);
                }
            }

            #pragma unroll
            for (int nt = 0; nt < 2; nt++) {
                const int slot = cc * 32 + wn * 16 + nt * 8 + 2 * t;
                const float aj0 = (slot < cnt) ? 1.f : 0.f;
                const float aj1 = (slot + 1 < cnt) ? 1.f : 0.f;
                #pragma unroll
                for (int mt = 0; mt < 2; mt++) {
                    best[mt * 2] = fmaxf(best[mt * 2],
                        fmaxf(acc[mt][nt][0] * aj0, acc[mt][nt][1] * aj1));
                    best[mt * 2 + 1] = fmaxf(best[mt * 2 + 1],
                        fmaxf(acc[mt][nt][2] * aj0, acc[mt][nt][3] * aj1));
                }
            }
            __syncthreads();
            try_stage_one(sb, efeat, adj, idxr, cntr, S, qs, tid);
            qc++;
        }

        // epilogue
        #pragma unroll
        for (int s = 0; s < 4; s++) {
            best[s] = fmaxf(best[s], __shfl_xor_sync(0xFFFFFFFFu, best[s], 1));
            best[s] = fmaxf(best[s], __shfl_xor_sync(0xFFFFFFFFu, best[s], 2));
        }
        __syncthreads();
        if (t == 0) {
            #pragma unroll
            for (int s = 0; s < 4; s++)
                bestsm[wn * 128 + wm * 32 + (s >> 1) * 16 + (s & 1) * 8 + g]
                    = best[s];
        }
        __syncthreads();
        if (tid < 128) {
            const float clampv = (cnt < Nn) ? 0.f : -FLT_MAX;
            bestsm[tid] = fmaxf(fmaxf(bestsm[tid], bestsm[128 + tid]), clampv);
        }
        __syncthreads();
        if (tid < 128) {
            float o = g_base[it * MIDn + tid];
            #pragma unroll 8
            for (int k = 0; k < MIDn; k++)
                o = fmaf(bestsm[k], __ldg(&Wo2[(k << 7) + tid]), o);
            out[it * MIDn + tid] = o;
        }

        it += GRID; ts++;
    }
}

// ========================================================================
extern "C" void kernel_launch(void* const* d_in, const int* in_sizes, int n_in,
                              void* d_out, int out_size)
{
    const float* hidden = (const float*)d_in[0];
    const float* nfeat  = (const float*)d_in[1];
    const float* efeat  = (const float*)d_in[2];
    const float* gfeat  = (const float*)d_in[3];
    const float* adj    = (const float*)d_in[4];
    const float* W1  = (const float*)d_in[5];
    const float* b1  = (const float*)d_in[6];
    const float* W2  = (const float*)d_in[7];
    const float* b2  = (const float*)d_in[8];
    const float* We  = (const float*)d_in[9];
    const float* be  = (const float*)d_in[10];
    const float* Wg  = (const float*)d_in[11];
    const float* bg  = (const float*)d_in[12];
    const float* Wo1 = (const float*)d_in[13];
    const float* bo1 = (const float*)d_in[14];
    const float* Wo2 = (const float*)d_in[15];
    const float* bo2 = (const float*)d_in[16];
    float* out = (float*)d_out;

    static int smem_set = 0;
    if (!smem_set) {
        cudaFuncSetAttribute(main_kernel,
                             cudaFuncAttributeMaxDynamicSharedMemorySize,
                             SM_TOTAL);
        smem_set = 1;
    }

    aux_kernel<<<296, 512>>>(hidden, nfeat, gfeat, W1, b1, W2, b2, We,
                             Wg, bg, Wo1, bo1, bo2);
    main_kernel<<<GRID, 256, SM_TOTAL>>>(efeat, adj, be, Wo2, out);
}

// round 13
// speedup vs baseline: 1.4095x; 1.4095x over previous
#include <cuda_runtime.h>
#include <cstdint>
#include <float.h>

// Problem constants
#define Bn    8
#define Nn    256
#define Dd    128
#define MIDn  128
#define FEATn 256   // 2*D
#define NTOT  (Bn * Nn)     // 2048 (b,j) tiles
#define GRID  296           // persistent: 2 CTAs x 148 SMs

// Scratch (device globals; no runtime allocation allowed)
__device__ float g_msg1[Bn * Nn * MIDn];
__device__ float g_msg2[Bn * Nn * MIDn];
__device__ float g_msgg[Bn * MIDn];
__device__ float g_base[Bn * Nn * MIDn];
__device__ unsigned g_WeTpack[MIDn * Dd];       // We^T fragment-packed (tf32 bits)

// ---------------- PTX helpers (arch-agnostic, sm_80+) --------------------
__device__ __forceinline__ uint32_t smem_u32(const void* p) {
    uint32_t a;
    asm("{ .reg .u64 t; cvta.to.shared.u64 t, %1; cvt.u32.u64 %0, t; }"
        : "=r"(a) : "l"(p));
    return a;
}
__device__ __forceinline__ void cp16(uint32_t dst, const void* src) {
    asm volatile("cp.async.cg.shared.global [%0], [%1], 16;"
                 :: "r"(dst), "l"(src) : "memory");
}
__device__ __forceinline__ void cp_commit() {
    asm volatile("cp.async.commit_group;" ::: "memory");
}
template <int N> __device__ __forceinline__ void cp_wait() {
    asm volatile("cp.async.wait_group %0;" :: "n"(N) : "memory");
}
__device__ __forceinline__ unsigned tf32r(float x) {
    unsigned u;
    asm("cvt.rna.tf32.f32 %0, %1;" : "=r"(u) : "f"(x));
    return u;
}
__device__ __forceinline__ void mma8(float* c, uint4 a, unsigned b0, unsigned b1) {
    asm volatile(
        "mma.sync.aligned.m16n8k8.row.col.f32.tf32.tf32.f32 "
        "{%0,%1,%2,%3},{%4,%5,%6,%7},{%8,%9},{%0,%1,%2,%3};"
        : "+f"(c[0]), "+f"(c[1]), "+f"(c[2]), "+f"(c[3])
        : "r"(a.x), "r"(a.y), "r"(a.z), "r"(a.w), "r"(b0), "r"(b1));
}

// ---------------- smem layout (bytes), 3-deep ring ------------------------
#define EPADB    576    // 144 floats: LDS.128 conflict-free
#define ECHUNKB  (32 * EPADB)               // 18432
#define M2PADB   528    // 132 floats: LDS.32 conflict-free
#define M2CHUNKB (32 * M2PADB)              // 16896
#define SM_E     0                          // 3 * 18432 = 55296
#define SM_M     55296                      // 3 * 16896 = 50688
#define SM_IDX0  106torr                    // placeholder (redefined below)
#undef  SM_IDX0
#define SM_IDX0  105984                     // 256 ints
#define SM_IDX1  107008                     // 256 ints
#define SM_CNT0  108032
#define SM_CNT1  108036
#define SM_BEST  108160                     // 128 floats
#define SM_TOTAL 108672

// ========================================================================
// Fused aux kernel (512 threads/block, 296 blocks):
//   [0,256)   : prep (msg1,msg2,base)
//   [256,288) : pack We^T A-fragments (deep k-relabel for LDS.128 B path)
//   [288,296) : msgg (tid<128)
// ========================================================================
__global__ __launch_bounds__(512) void aux_kernel(
    const float* __restrict__ hidden, const float* __restrict__ nfeat,
    const float* __restrict__ gfeat,
    const float* __restrict__ W1, const float* __restrict__ b1,
    const float* __restrict__ W2, const float* __restrict__ b2,
    const float* __restrict__ We,
    const float* __restrict__ Wg, const float* __restrict__ bg,
    const float* __restrict__ Wo1, const float* __restrict__ bo1,
    const float* __restrict__ bo2)
{
    const int tid = threadIdx.x;
    if (blockIdx.x >= 288) {                       // ---- msgg ----
        if (tid < 128) {
            const int b = blockIdx.x - 288, m = tid;
            float acc = bg[m];
            #pragma unroll 8
            for (int k = 0; k < Dd; k++)
                acc = fmaf(gfeat[b * Dd + k], __ldg(&Wg[k * MIDn + m]), acc);
            g_msgg[b * MIDn + m] = acc;
        }
        return;
    }
    if (blockIdx.x >= 256) {                       // ---- A pack ----
        const int idx = (blockIdx.x - 256) * 512 + tid;   // 0..16383
        const int blk = idx >> 7;                  // mtg16*16 + kt
        const int mtg = blk >> 4, kt = blk & 15;
        const int l = (idx >> 2) & 31, e = idx & 3;
        const int m = mtg * 16 + (l >> 2) + (e & 1) * 8;
        // deep relabel: matches LDS.128 B feed (verified in R9)
        const int k = ((kt >> 1) << 4) + 4 * (l & 3) + ((kt & 1) << 1)
                    + (e >> 1);
        g_WeTpack[idx] = tf32r(We[k * MIDn + m]);
        return;
    }
    // ---- prep: 8 rows, f split 4 ways ----
    __shared__ float fs[8 * FEATn];
    __shared__ float red[3][3 * 1024];
    const int m = tid & 127, h = tid >> 7;
    const int row0 = blockIdx.x * 8;

    for (int idx = tid; idx < 8 * FEATn; idx += 512) {
        int r = idx >> 8, c = idx & 255;
        fs[idx] = (c < Dd) ? nfeat[(row0 + r) * Dd + c]
                           : hidden[(row0 + r) * Dd + (c - Dd)];
    }
    __syncthreads();

    float a1[8], a2[8], ao[8];
    #pragma unroll
    for (int r = 0; r < 8; r++) { a1[r] = 0.f; a2[r] = 0.f; ao[r] = 0.f; }

    const int fbase = h * 64;
    #pragma unroll 4
    for (int ff = 0; ff < 64; ff++) {
        const int f = fbase + ff;
        const float w1 = __ldg(&W1[f * MIDn + m]);
        const float w2 = __ldg(&W2[f * MIDn + m]);
        const float wo = __ldg(&Wo1[f * MIDn + m]);
        #pragma unroll
        for (int r = 0; r < 8; r++) {
            const float s = fs[r * FEATn + f];
            a1[r] = fmaf(s, w1, a1[r]);
            a2[r] = fmaf(s, w2, a2[r]);
            ao[r] = fmaf(s, wo, ao[r]);
        }
    }
    if (h > 0) {
        #pragma unroll
        for (int r = 0; r < 8; r++) {
            red[h - 1][0 * 1024 + r * 128 + m] = a1[r];
            red[h - 1][1 * 1024 + r * 128 + m] = a2[r];
            red[h - 1][2 * 1024 + r * 128 + m] = ao[r];
        }
    }
    __syncthreads();
    if (h == 0) {
        const float bb1 = b1[m], bb2 = b2[m], bbo = bo1[m] + bo2[m];
        #pragma unroll
        for (int r = 0; r < 8; r++) {
            const int row = row0 + r;
            const int o = r * 128 + m;
            g_msg1[row * MIDn + m] = a1[r] + red[0][o] + red[1][o]
                                   + red[2][o] + bb1;
            g_msg2[row * MIDn + m] = a2[r] + red[0][1024 + o] + red[1][1024 + o]
                                   + red[2][1024 + o] + bb2;
            g_base[row * MIDn + m] = ao[r] + red[0][2048 + o] + red[1][2048 + o]
                                   + red[2][2048 + o] + bbo;
        }
    }
}

// ========================================================================
// Persistent main kernel: 128 threads, 4 warps (m-tile 32 each), 2 CTAs/SM.
// 3-deep chunk ring; 1 commit per chunk-slot (prefill 3, loop 1, splice 3).
// ========================================================================
__device__ __forceinline__ void stage_chunk(uint32_t sb, const float* ebj,
                                            const float* m2g,
                                            const int* idxp, int buf,
                                            int w, int l)
{
    const uint32_t ebuf = sb + SM_E + buf * ECHUNKB;
    const uint32_t mbuf = sb + SM_M + buf * M2CHUNKB;
    #pragma unroll
    for (int rr = 0; rr < 8; rr++) {
        const int r = w + rr * 4;                 // 0..31
        const long i = idxp[r];
        cp16(ebuf + r * EPADB + l * 16, ebj + i * (Nn * Dd) + l * 4);
        cp16(mbuf + r * M2PADB + l * 16, m2g + i * MIDn + l * 4);
    }
}

__device__ __forceinline__ int build_list(const float* __restrict__ adjcol,
                                          int* idxd, int* cntd,
                                          int tid, int w, int l)
{
    if (tid == 0) *cntd = 0;
    __syncthreads();
    #pragma unroll
    for (int pp = 0; pp < 2; pp++) {
        const int i = (w * 2 + pp) * 32 + l;
        const float a = adjcol[(long)i * Nn];
        const unsigned mask = __ballot_sync(0xFFFFFFFFu, a != 0.f);
        int basep = 0;
        if (l == 0) basep = atomicAdd(cntd, __popc(mask));
        basep = __shfl_sync(0xFFFFFFFFu, basep, 0);
        if (a != 0.f) idxd[basep + __popc(mask & ((1u << l) - 1))] = i;
    }
    __syncthreads();
    const int cnt = *cntd;
    for (int s = cnt + tid; s < 256; s += 128) idxd[s] = 0;
    __syncthreads();
    return cnt;
}

__global__ __launch_bounds__(128, 2) void main_kernel(
    const float* __restrict__ efeat, const float* __restrict__ adj,
    const float* __restrict__ be,    const float* __restrict__ Wo2,
    float* __restrict__ out)
{
    extern __shared__ __align__(16) char smem[];
    const uint32_t sb = smem_u32(smem);
    const int tid = threadIdx.x;
    const int w = tid >> 5, l = tid & 31, g = l >> 2, t = l & 3;

    int* idxb[2] = { (int*)(smem + SM_IDX0), (int*)(smem + SM_IDX1) };
    int* cntb[2] = { (int*)(smem + SM_CNT0), (int*)(smem + SM_CNT1) };
    float* bestsm = (float*)(smem + SM_BEST);

    // A fragments for this warp's 32-row m-tile (128 regs)
    uint4 A[2][16];
    #pragma unroll
    for (int mt = 0; mt < 2; mt++)
        #pragma unroll
        for (int kt = 0; kt < 16; kt++)
            A[mt][kt] = *(const uint4*)(g_WeTpack
                         + (((w * 2 + mt) * 16 + kt) << 7) + (l << 2));

    int it = blockIdx.x;
    int buf = 0;           // idx double-buffer selector
    int qs = 0, qc = 0;    // staged / consumed real-chunk counters (ring 3)
    int cnt_cur;
    {   // first tile: list + 3-deep prefill (3 commits)
        const int b = it >> 8, j = it & 255;
        cnt_cur = build_list(adj + (long)b * Nn * Nn + j,
                             idxb[0], cntb[0], tid, w, l);
        const float* ebj = efeat + (long)b * (Nn * Nn * Dd) + (long)j * Dd;
        const float* m2g = g_msg2 + ((long)b << 15);
        const int nc = (cnt_cur + 31) >> 5;
        #pragma unroll
        for (int q = 0; q < 3; q++) {
            if (q < nc) { stage_chunk(sb, ebj, m2g, idxb[0] + q * 32,
                                      qs % 3, w, l); qs++; }
            cp_commit();
        }
    }

    while (it < NTOT) {
        const int b = it >> 8, j = it & 255;
        const float* ebj = efeat + (long)b * (Nn * Nn * Dd) + (long)j * Dd;
        const float* m2g = g_msg2 + ((long)b << 15);
        const int* idxc = idxb[buf];
        const int cnt = cnt_cur;
        const int nc = (cnt + 31) >> 5;

        float cm[4], best[4];
        #pragma unroll
        for (int s = 0; s < 4; s++) {
            const int m = w * 32 + (s >> 1) * 16 + (s & 1) * 8 + g;
            cm[s] = g_msg1[it * MIDn + m] + g_msgg[b * MIDn + m] + be[m];
            best[s] = -FLT_MAX;
        }

        #pragma unroll 1
        for (int c = 0; c < nc; c++) {
            cp_wait<2>();
            __syncthreads();
            const int bufc = qc % 3;
            const char* eb = smem + SM_E + bufc * ECHUNKB;
            const float* m2s = (const float*)(smem + SM_M + bufc * M2CHUNKB);

            // acc init = msg2 + cst (folded into mma C chain)
            float acc[2][4][4];
            #pragma unroll
            for (int nt = 0; nt < 4; nt++) {
                const int il = nt * 8 + 2 * t;
                #pragma unroll
                for (int mt = 0; mt < 2; mt++) {
                    const int mlo = w * 32 + mt * 16 + g;
                    acc[mt][nt][0] = m2s[il * 132 + mlo] + cm[mt * 2];
                    acc[mt][nt][1] = m2s[(il + 1) * 132 + mlo] + cm[mt * 2];
                    acc[mt][nt][2] = m2s[il * 132 + mlo + 8] + cm[mt * 2 + 1];
                    acc[mt][nt][3] = m2s[(il + 1) * 132 + mlo + 8]
                                   + cm[mt * 2 + 1];
                }
            }

            #pragma unroll
            for (int ktp = 0; ktp < 8; ktp++) {
                #pragma unroll
                for (int nt = 0; nt < 4; nt++) {
                    const float4 f = *(const float4*)(eb
                        + (nt * 8 + g) * EPADB + ktp * 64 + t * 16);
                    const unsigned f0 = __float_as_uint(f.x);
                    const unsigned f1 = __float_as_uint(f.y);
                    const unsigned f2 = __float_as_uint(f.z);
                    const unsigned f3 = __float_as_uint(f.w);
                    mma8(acc[0][nt], A[0][2 * ktp], f0, f1);
                    mma8(acc[1][nt], A[1][2 * ktp], f0, f1);
                    mma8(acc[0][nt], A[0][2 * ktp + 1], f2, f3);
                    mma8(acc[1][nt], A[1][2 * ktp + 1], f2, f3);
                }
            }

            #pragma unroll
            for (int nt = 0; nt < 4; nt++) {
                const int slot = c * 32 + nt * 8 + 2 * t;
                const float aj0 = (slot < cnt) ? 1.f : 0.f;
                const float aj1 = (slot + 1 < cnt) ? 1.f : 0.f;
                #pragma unroll
                for (int mt = 0; mt < 2; mt++) {
                    best[mt * 2] = fmaxf(best[mt * 2],
                        fmaxf(acc[mt][nt][0] * aj0, acc[mt][nt][1] * aj1));
                    best[mt * 2 + 1] = fmaxf(best[mt * 2 + 1],
                        fmaxf(acc[mt][nt][2] * aj0, acc[mt][nt][3] * aj1));
                }
            }
            __syncthreads();
            if (c + 3 < nc) { stage_chunk(sb, ebj, m2g, idxc + (c + 3) * 32,
                                          qs % 3, w, l); qs++; }
            cp_commit();
            qc++;
        }

        // --- splice: build + 3-deep prefill of NEXT tile before epilogue ---
        const int itn = it + GRID;
        if (itn < NTOT) {
            const int bn = itn >> 8, jn = itn & 255;
            cnt_cur = build_list(adj + (long)bn * Nn * Nn + jn,
                                 idxb[buf ^ 1], cntb[buf ^ 1], tid, w, l);
            const float* ebjn = efeat + (long)bn * (Nn * Nn * Dd)
                                + (long)jn * Dd;
            const float* m2gn = g_msg2 + ((long)bn << 15);
            const int ncn = (cnt_cur + 31) >> 5;
            #pragma unroll
            for (int q = 0; q < 3; q++) {
                if (q < ncn) { stage_chunk(sb, ebjn, m2gn,
                                           idxb[buf ^ 1] + q * 32,
                                           qs % 3, w, l); qs++; }
                cp_commit();
            }
        }

        // --- epilogue (overlaps next tile's fill) ---
        if (cnt < Nn) {
            #pragma unroll
            for (int s = 0; s < 4; s++) best[s] = fmaxf(best[s], 0.f);
        }
        #pragma unroll
        for (int s = 0; s < 4; s++) {
            best[s] = fmaxf(best[s], __shfl_xor_sync(0xFFFFFFFFu, best[s], 1));
            best[s] = fmaxf(best[s], __shfl_xor_sync(0xFFFFFFFFu, best[s], 2));
        }
        __syncthreads();
        if (t == 0) {
            #pragma unroll
            for (int s = 0; s < 4; s++)
                bestsm[w * 32 + (s >> 1) * 16 + (s & 1) * 8 + g] = best[s];
        }
        __syncthreads();

        float o = g_base[it * MIDn + tid];
        #pragma unroll 8
        for (int k = 0; k < MIDn; k++)
            o = fmaf(bestsm[k], __ldg(&Wo2[(k << 7) + tid]), o);
        out[it * MIDn + tid] = o;

        buf ^= 1;
        it = itn;
    }
}

// ========================================================================
extern "C" void kernel_launch(void* const* d_in, const int* in_sizes, int n_in,
                              void* d_out, int out_size)
{
    const float* hidden = (const float*)d_in[0];
    const float* nfeat  = (const float*)d_in[1];
    const float* efeat  = (const float*)d_in[2];
    const float* gfeat  = (const float*)d_in[3];
    const float* adj    = (const float*)d_in[4];
    const float* W1  = (const float*)d_in[5];
    const float* b1  = (const float*)d_in[6];
    const float* W2  = (const float*)d_in[7];
    const float* b2  = (const float*)d_in[8];
    const float* We  = (const float*)d_in[9];
    const float* be  = (const float*)d_in[10];
    const float* Wg  = (const float*)d_in[11];
    const float* bg  = (const float*)d_in[12];
    const float* Wo1 = (const float*)d_in[13];
    const float* bo1 = (const float*)d_in[14];
    const float* Wo2 = (const float*)d_in[15];
    const float* bo2 = (const float*)d_in[16];
    float* out = (float*)d_out;

    static int smem_set = 0;
    if (!smem_set) {
        cudaFuncSetAttribute(main_kernel,
                             cudaFuncAttributeMaxDynamicSharedMemorySize,
                             SM_TOTAL);
        smem_set = 1;
    }

    aux_kernel<<<296, 512>>>(hidden, nfeat, gfeat, W1, b1, W2, b2, We,
                             Wg, bg, Wo1, bo1, bo2);
    main_kernel<<<GRID, 128, SM_TOTAL>>>(efeat, adj, be, Wo2, out);
}